// round 10
// baseline (speedup 1.0000x reference)
#include <cuda_runtime.h>
#include <math.h>

// Problem constants (fixed shapes from reference setup_inputs)
#define BATCH 16
#define CIN   128
#define C2    256     // 2*CIN (cos plane + sin plane)
#define COUT  256
#define HW    56
#define PIX   (HW*HW) // 3136
#define TAPS  9

typedef unsigned long long u64;

// Scratch (device globals: allocation-free per harness rules)
__device__ __align__(16) float g_inp[BATCH * C2 * PIX];   // [b][c2][y][x], 51.4 MB
// Interleaved weights: [(c2*9+tap)*128 + cp] * 4 floats = (wr_even, wr_odd,
// wi_even, wi_odd) for cout pair cp = cout>>1. 4.7 MB.
__device__ __align__(16) float g_w[C2 * TAPS * 128 * 4];

// ---- Blackwell packed f32x2 ops (two independent IEEE fp32 lanes) ----
__device__ __forceinline__ u64 fma2(u64 a, u64 b, u64 c) {
    u64 d;
    asm("fma.rn.f32x2 %0, %1, %2, %3;" : "=l"(d) : "l"(a), "l"(b), "l"(c));
    return d;
}
__device__ __forceinline__ u64 add2(u64 a, u64 b) {
    u64 d;
    asm("add.rn.f32x2 %0, %1, %2;" : "=l"(d) : "l"(a), "l"(b));
    return d;
}
// exact IEEE negation of both lanes
#define NEG2(x) ((x) ^ 0x8000000080000000ULL)

__device__ __forceinline__ void unpack2(u64 v, float& lo, float& hi) {
    asm("mov.b64 {%0, %1}, %2;" : "=f"(lo), "=f"(hi) : "l"(v));
}

// ---------------------------------------------------------------------------
// Merged prep kernel (2 launches total -> ncu -s 5 lands on ring_conv)
//  i < N1: input planes  cos(x)->[0,128), sin(x)->[128,256)   (pure fp32)
//  else  : trig weight products, written in interleaved pair layout.
// probe/out layout: (1, Cin, Cout, 1, 1, 3, 3) -> flat ((cin*COUT+cout)*9+tap)
// ---------------------------------------------------------------------------
#define N1 (BATCH * CIN * PIX)
#define N2 (CIN * COUT * TAPS)

__global__ void prep_all(const float* __restrict__ x,
                         const float* __restrict__ probe,
                         const float* __restrict__ outang) {
    int i = blockIdx.x * blockDim.x + threadIdx.x;
    if (i < N1) {
        float v = x[i];
        int b   = i / (CIN * PIX);
        int rem = i % (CIN * PIX);
        int c   = rem / PIX;
        int p   = rem % PIX;
        float s, cs;
        sincosf(v, &s, &cs);
        g_inp[(b * C2 + c) * PIX + p]        = cs;
        g_inp[(b * C2 + c + CIN) * PIX + p]  = s;
    } else {
        int j = i - N1;
        if (j >= N2) return;
        int cin  = j / (COUT * TAPS);
        int rem  = j % (COUT * TAPS);
        int cout = rem / TAPS;
        int tap  = rem % TAPS;
        float p = probe[j];
        float o = outang[j];
        float sp, cp, so, co;
        sincosf(p, &sp, &cp);
        sincosf(o, &so, &co);
        int cpair = cout >> 1;
        int par   = cout & 1;
        // c2 = cin (cos plane): wr = cp*co, wi = cp*so
        {
            float* base = &g_w[((cin * TAPS + tap) * 128 + cpair) * 4];
            base[par]     = cp * co;
            base[2 + par] = cp * so;
        }
        // c2 = cin + 128 (sin plane): wr = sp*co, wi = sp*so
        {
            float* base = &g_w[(((cin + CIN) * TAPS + tap) * 128 + cpair) * 4];
            base[par]     = sp * co;
            base[2 + par] = sp * so;
        }
    }
}

// ---------------------------------------------------------------------------
// Main conv kernel: f32x2-packed FMAs over cout-pairs, chunked + Kahan
// (negated-compensation form). Single-buffered smem (double-buffer regressed
// in R9: +regs, occupancy-starved).
//
// Grid: (4 cout-slices of 64, 49 spatial tiles of 8x8, 16 batch).
// Block: 256 threads. Swizzled lane mapping for LDS wavefront minimization:
//   ctl = (tid&7) | ((tid>>5)&1)<<3     (16 cout lanes; 8 distinct per warp)
//   pl  = ((tid>>3)&3) | ((tid>>6)&3)<<2 (16 pixel lanes; 4 distinct per warp)
// Thread couts: cout = coutBase + 2*(ctl + jp*16) + lane, jp in {0,1}.
//   -> weight LDS.128 addresses are 8 consecutive 16B slots per warp
//      (128B, conflict-free, 1 wavefront; was 2).
// Thread pixels: row = pl>>1 (0..7), cols (pl&1)*4 + 0..3.
//   -> input LDS.128: 4 distinct 16B addrs, bank-distinct, 1 wavefront.
// Per-output accumulation order (icl -> ky -> kx, chunk partial, Kahan merge)
// is bit-identical to the 2795.8us R7 kernel.
// ---------------------------------------------------------------------------
#define CHUNK 4
#define W_FLOATS (CHUNK * TAPS * 32 * 4)    // 4608 floats (64-cout slice)
#define W_VEC4   (W_FLOATS / 4)             // 1152 float4
#define IN_PTS   (CHUNK * 10 * 10)          // 400 halo points (stored as float2)
#define NCHUNK   (C2 / CHUNK)               // 64

__global__ __launch_bounds__(256)
void ring_conv(float* __restrict__ dout) {
    __shared__ __align__(16) float  s_w[W_FLOATS];
    __shared__ __align__(16) float2 s_in[IN_PTS];

    const int tid = threadIdx.x;
    const int ctl = (tid & 7) | (((tid >> 5) & 1) << 3);   // 0..15
    const int pl  = ((tid >> 3) & 3) | (((tid >> 6) & 3) << 2); // 0..15
    const int row  = pl >> 1;           // 0..7
    const int colb = (pl & 1) * 4;      // 0 or 4

    const int coutBase = blockIdx.x * 64;
    const int cpBase   = blockIdx.x * 32;   // cout-pair base
    const int t     = blockIdx.y;
    const int tileY = (t / 7) * 8;
    const int tileX = (t % 7) * 8;
    const int b     = blockIdx.z;

    // s = main sum, nc = NEGATED Kahan compensation
    u64 sRe[2][4], sIm[2][4];
    u64 ncRe[2][4], ncIm[2][4];
#pragma unroll
    for (int jp = 0; jp < 2; ++jp)
#pragma unroll
        for (int k = 0; k < 4; ++k) {
            sRe[jp][k] = 0ull; sIm[jp][k] = 0ull;
            ncRe[jp][k] = 0ull; ncIm[jp][k] = 0ull;
        }

    for (int chunk = 0; chunk < NCHUNK; ++chunk) {
        const int ic0 = chunk * CHUNK;
        __syncthreads();   // protect smem reads of previous chunk

        // ---- load input halo tile: CHUNK x 10 x 10, duplicated (v,v) ----
#pragma unroll
        for (int it = 0; it < 2; ++it) {
            int i = tid + it * 256;
            if (i < IN_PTS) {
                int icl = i / 100;
                int p   = i % 100;
                int gy  = tileY + p / 10 - 1;
                int gx  = tileX + p % 10 - 1;
                float v = 0.f;
                if ((unsigned)gy < (unsigned)HW && (unsigned)gx < (unsigned)HW)
                    v = g_inp[((b * C2 + ic0 + icl) * HW + gy) * HW + gx];
                s_in[i] = make_float2(v, v);
            }
        }

        // ---- load weights: CHUNK*9*32 float4 = 1152 float4 ----
        // smem layout: [(icl*9+tap)*32 + cp_local] * 16B, identical order to
        // the global slice -> contiguous float4 copy.
#pragma unroll
        for (int it = 0; it < 5; ++it) {
            int i = tid + it * 256;          // float4 index
            if (i < W_VEC4) {
                int ict = i >> 5;            // icl*9 + tap, 0..35
                int cpl = i & 31;            // cp_local
                reinterpret_cast<float4*>(s_w)[i] =
                    *reinterpret_cast<const float4*>(
                        &g_w[(((ic0 * TAPS) + ict) * 128 + cpBase + cpl) * 4]);
            }
        }

        __syncthreads();

        // ---- compute chunk partial (packed FMA, bit-identical order) ----
        u64 pRe[2][4], pIm[2][4];
#pragma unroll
        for (int jp = 0; jp < 2; ++jp)
#pragma unroll
            for (int k = 0; k < 4; ++k) { pRe[jp][k] = 0ull; pIm[jp][k] = 0ull; }

#pragma unroll
        for (int icl = 0; icl < CHUNK; ++icl) {
            const float2* in_base = &s_in[icl * 100];
#pragma unroll
            for (int ky = 0; ky < 3; ++ky) {
                // 6 duplicated (v,v) operands, loaded as 3x LDS.128
                u64 vp[6];
                const ulonglong2* rp = reinterpret_cast<const ulonglong2*>(
                    &in_base[(row + ky) * 10 + colb]);
#pragma unroll
                for (int j = 0; j < 3; ++j) {
                    ulonglong2 q = rp[j];
                    vp[2 * j]     = q.x;
                    vp[2 * j + 1] = q.y;
                }
#pragma unroll
                for (int kx = 0; kx < 3; ++kx) {
                    const int tap = ky * 3 + kx;
#pragma unroll
                    for (int jp = 0; jp < 2; ++jp) {
                        // one LDS.128 yields (wr pair, wi pair) for this
                        // thread's cout pair; warp lanes are 8 consecutive
                        // 16B slots -> conflict-free broadcast-grade access
                        const ulonglong2 q = reinterpret_cast<const ulonglong2*>(
                            s_w)[(icl * TAPS + tap) * 32 + ctl + jp * 16];
                        const u64 wr = q.x;
                        const u64 wi = q.y;
#pragma unroll
                        for (int k = 0; k < 4; ++k) {
                            u64 xv = vp[k + kx];
                            // Re/Im pair shares b-operand xv -> reuse hit
                            pRe[jp][k] = fma2(wr, xv, pRe[jp][k]);
                            pIm[jp][k] = fma2(wi, xv, pIm[jp][k]);
                        }
                    }
                }
            }
        }

        // ---- Kahan merge (negated-compensation; exact IEEE negation) ----
#pragma unroll
        for (int jp = 0; jp < 2; ++jp) {
#pragma unroll
            for (int k = 0; k < 4; ++k) {
                {
                    u64 y1 = add2(pRe[jp][k], ncRe[jp][k]);
                    u64 tt = add2(sRe[jp][k], y1);
                    ncRe[jp][k] = add2(add2(sRe[jp][k], NEG2(tt)), y1);
                    sRe[jp][k] = tt;
                }
                {
                    u64 y1 = add2(pIm[jp][k], ncIm[jp][k]);
                    u64 tt = add2(sIm[jp][k], y1);
                    ncIm[jp][k] = add2(add2(sIm[jp][k], NEG2(tt)), y1);
                    sIm[jp][k] = tt;
                }
            }
        }
    }

    // ---- epilogue: angle = atan2(im, re) ----
    const int y = tileY + row;
#pragma unroll
    for (int jp = 0; jp < 2; ++jp) {
#pragma unroll
        for (int lane = 0; lane < 2; ++lane) {
            const int cout = coutBase + (ctl + jp * 16) * 2 + lane;
            float* op = &dout[((b * COUT + cout) * HW + y) * HW + tileX + colb];
#pragma unroll
            for (int k = 0; k < 4; ++k) {
                float reLo, reHi, imLo, imHi;
                unpack2(sRe[jp][k], reLo, reHi);
                unpack2(sIm[jp][k], imLo, imHi);
                float re = lane ? reHi : reLo;
                float im = lane ? imHi : imLo;
                op[k] = atan2f(im, re);
            }
        }
    }
}

// ---------------------------------------------------------------------------
extern "C" void kernel_launch(void* const* d_in, const int* in_sizes, int n_in,
                              void* d_out, int out_size) {
    const float* x      = (const float*)d_in[0];
    const float* probe  = (const float*)d_in[1];
    const float* outang = (const float*)d_in[2];
    float* dout = (float*)d_out;

    (void)in_sizes; (void)n_in; (void)out_size;

    const int ntot = N1 + N2;
    prep_all<<<(ntot + 255) / 256, 256>>>(x, probe, outang);

    dim3 grid(4, 49, BATCH);
    ring_conv<<<grid, 256>>>(dout);
}

// round 12
// speedup vs baseline: 1.0817x; 1.0817x over previous
#include <cuda_runtime.h>
#include <math.h>
#include <stdint.h>

// Problem constants (fixed shapes from reference setup_inputs)
#define BATCH 16
#define CIN   128
#define C2    256     // 2*CIN (cos plane + sin plane)
#define COUT  256
#define HW    56
#define PIX   (HW*HW) // 3136
#define TAPS  9

typedef unsigned long long u64;

// Scratch (device globals: allocation-free per harness rules)
// Input planes stored DUPLICATED (v,v) as float2 so cp.async can copy the
// packed-FMA broadcast operand directly. 103 MB.
__device__ __align__(16) float2 g_inp2[BATCH * C2 * PIX];
// Weights, R7 layout: [(c2*9+tap)*2+ri][cout]. 4.7 MB.
__device__ __align__(16) float g_w[C2 * TAPS * 2 * COUT];

// ---- Blackwell packed f32x2 ops (two independent IEEE fp32 lanes) ----
__device__ __forceinline__ u64 fma2(u64 a, u64 b, u64 c) {
    u64 d;
    asm("fma.rn.f32x2 %0, %1, %2, %3;" : "=l"(d) : "l"(a), "l"(b), "l"(c));
    return d;
}
__device__ __forceinline__ u64 add2(u64 a, u64 b) {
    u64 d;
    asm("add.rn.f32x2 %0, %1, %2;" : "=l"(d) : "l"(a), "l"(b));
    return d;
}
#define NEG2(x) ((x) ^ 0x8000000080000000ULL)

__device__ __forceinline__ void unpack2(u64 v, float& lo, float& hi) {
    asm("mov.b64 {%0, %1}, %2;" : "=f"(lo), "=f"(hi) : "l"(v));
}

// ---- cp.async helpers ----
__device__ __forceinline__ void cp16(uint32_t saddr, const void* g) {
    asm volatile("cp.async.cg.shared.global [%0], [%1], 16;"
                 :: "r"(saddr), "l"(g));
}
// 8B copy; when szr==0 the destination is zero-filled (src not read).
__device__ __forceinline__ void cp8z(uint32_t saddr, const void* g, int szr) {
    asm volatile("cp.async.ca.shared.global [%0], [%1], 8, %2;"
                 :: "r"(saddr), "l"(g), "r"(szr));
}
#define CP_COMMIT() asm volatile("cp.async.commit_group;" ::: "memory")
#define CP_WAIT0()  asm volatile("cp.async.wait_group 0;"  ::: "memory")

// ---------------------------------------------------------------------------
// Merged prep kernel (2 launches total).
//  i < N1: input planes  cos(x)->[0,128), sin(x)->[128,256), duplicated (v,v)
//  else  : trig weight products (R7 layout)
// probe/out layout: (1, Cin, Cout, 1, 1, 3, 3) -> flat ((cin*COUT+cout)*9+tap)
// ---------------------------------------------------------------------------
#define N1 (BATCH * CIN * PIX)
#define N2 (CIN * COUT * TAPS)

__global__ void prep_all(const float* __restrict__ x,
                         const float* __restrict__ probe,
                         const float* __restrict__ outang) {
    int i = blockIdx.x * blockDim.x + threadIdx.x;
    if (i < N1) {
        float v = x[i];
        int b   = i / (CIN * PIX);
        int rem = i % (CIN * PIX);
        int c   = rem / PIX;
        int p   = rem % PIX;
        float s, cs;
        sincosf(v, &s, &cs);
        g_inp2[(b * C2 + c) * PIX + p]        = make_float2(cs, cs);
        g_inp2[(b * C2 + c + CIN) * PIX + p]  = make_float2(s, s);
    } else {
        int j = i - N1;
        if (j >= N2) return;
        int cin  = j / (COUT * TAPS);
        int rem  = j % (COUT * TAPS);
        int cout = rem / TAPS;
        int tap  = rem % TAPS;
        float p = probe[j];
        float o = outang[j];
        float sp, cp, so, co;
        sincosf(p, &sp, &cp);
        sincosf(o, &so, &co);
        g_w[(( cin        * TAPS + tap) * 2 + 0) * COUT + cout] = cp * co;
        g_w[(( cin        * TAPS + tap) * 2 + 1) * COUT + cout] = cp * so;
        g_w[(((cin + CIN) * TAPS + tap) * 2 + 0) * COUT + cout] = sp * co;
        g_w[(((cin + CIN) * TAPS + tap) * 2 + 1) * COUT + cout] = sp * so;
    }
}

// ---------------------------------------------------------------------------
// Main conv kernel: R7 compute (bit-identical), cp.async double-buffered
// smem pipeline (register-free prefetch; R9 showed register prefetch kills
// occupancy). One __syncthreads per chunk; chunk c+1 copies fly during
// chunk c compute.
//
// Grid: (4 cout-quarters of 64, 49 spatial tiles of 8x8, 16 batch).
// Block: 256 threads = 16 cout-lanes x 16 pixel-lanes (R7 mapping).
// ---------------------------------------------------------------------------
#define CHUNK 4
#define W_FLOATS (CHUNK * TAPS * 2 * 64)    // 4608 floats (64-cout slice)
#define W_VEC4   (W_FLOATS / 4)             // 1152 float4
#define IN_PTS   (CHUNK * 10 * 10)          // 400 halo points (float2 (v,v))
#define NCHUNK   (C2 / CHUNK)               // 64

__global__ __launch_bounds__(256)
void ring_conv(float* __restrict__ dout) {
    __shared__ __align__(16) float  s_w[2][W_FLOATS];
    __shared__ __align__(16) float2 s_in[2][IN_PTS];

    const int tid  = threadIdx.x;
    const int ct   = tid & 15;          // cout lane (4 couts each)
    const int pl   = tid >> 4;          // pixel lane 0..15
    const int row  = pl >> 1;           // 0..7
    const int colb = (pl & 1) * 4;      // 0 or 4

    const int coutBase = blockIdx.x * 64;
    const int t     = blockIdx.y;
    const int tileY = (t / 7) * 8;
    const int tileX = (t % 7) * 8;
    const int b     = blockIdx.z;

    // Per-thread copy descriptors (computed once; reused every chunk).
    // Input: up to 2 points per thread.
    int  in_idx[2];     // halo point index (or -1)
    int  in_sz[2];      // 8 = copy, 0 = zero-fill (OOB)
    long in_off[2];     // gmem float2 offset within channel plane stride
#pragma unroll
    for (int it = 0; it < 2; ++it) {
        int i = tid + it * 256;
        if (i < IN_PTS) {
            int icl = i / 100;
            int p   = i % 100;
            int gy  = tileY + p / 10 - 1;
            int gx  = tileX + p % 10 - 1;
            bool ok = (unsigned)gy < (unsigned)HW && (unsigned)gx < (unsigned)HW;
            in_idx[it] = i;
            in_sz[it]  = ok ? 8 : 0;
            in_off[it] = ok ? ((long)(b * C2 + icl) * PIX + gy * HW + gx) : 0;
        } else {
            in_idx[it] = -1; in_sz[it] = 0; in_off[it] = 0;
        }
    }

    uint32_t s_in_base = (uint32_t)__cvta_generic_to_shared(&s_in[0][0]);
    uint32_t s_w_base  = (uint32_t)__cvta_generic_to_shared(&s_w[0][0]);
    const uint32_t IN_BUF_B = IN_PTS * 8;        // bytes per input buffer
    const uint32_t W_BUF_B  = W_FLOATS * 4;      // bytes per weight buffer

    // Issue all cp.async copies for one chunk into buffer `buf`.
    auto issue_chunk = [&](int chunk, int buf) {
        const int ic0 = chunk * CHUNK;
        // inputs (8B, zero-filled when OOB). Channel advance = ic0 planes.
#pragma unroll
        for (int it = 0; it < 2; ++it) {
            if (in_idx[it] >= 0) {
                const float2* g = &g_inp2[in_off[it] + (long)ic0 * PIX];
                cp8z(s_in_base + buf * IN_BUF_B + in_idx[it] * 8, g, in_sz[it]);
            }
        }
        // weights (16B)
#pragma unroll
        for (int it = 0; it < 5; ++it) {
            int i = tid + it * 256;          // float4 index
            if (i < W_VEC4) {
                int f   = i * 4;
                int icl = f / (TAPS * 2 * 64);
                int r   = (f % (TAPS * 2 * 64)) / 64;   // tap*2 + ri
                int col = f & 63;
                cp16(s_w_base + buf * W_BUF_B + i * 16,
                     &g_w[((ic0 + icl) * 18 + r) * COUT + coutBase + col]);
            }
        }
        CP_COMMIT();
    };

    // Prologue: start chunk 0 into buffer 0.
    issue_chunk(0, 0);

    // s = main sum, nc = NEGATED Kahan compensation
    u64 sRe[2][4], sIm[2][4];
    u64 ncRe[2][4], ncIm[2][4];
#pragma unroll
    for (int jp = 0; jp < 2; ++jp)
#pragma unroll
        for (int k = 0; k < 4; ++k) {
            sRe[jp][k] = 0ull; sIm[jp][k] = 0ull;
            ncRe[jp][k] = 0ull; ncIm[jp][k] = 0ull;
        }

    for (int chunk = 0; chunk < NCHUNK; ++chunk) {
        const int cur = chunk & 1;

        CP_WAIT0();        // this chunk's copies (only group in flight) done
        __syncthreads();   // visibility + everyone done reading other buffer

        if (chunk + 1 < NCHUNK)
            issue_chunk(chunk + 1, cur ^ 1);   // flies during compute below

        // ---- compute chunk partial (packed FMA, bit-identical to R7) ----
        u64 pRe[2][4], pIm[2][4];
#pragma unroll
        for (int jp = 0; jp < 2; ++jp)
#pragma unroll
            for (int k = 0; k < 4; ++k) { pRe[jp][k] = 0ull; pIm[jp][k] = 0ull; }

#pragma unroll
        for (int icl = 0; icl < CHUNK; ++icl) {
            const float2* in_base = &s_in[cur][icl * 100];
#pragma unroll
            for (int ky = 0; ky < 3; ++ky) {
                u64 vp[6];
                const ulonglong2* rp = reinterpret_cast<const ulonglong2*>(
                    &in_base[(row + ky) * 10 + colb]);
#pragma unroll
                for (int j = 0; j < 3; ++j) {
                    ulonglong2 q = rp[j];
                    vp[2 * j]     = q.x;
                    vp[2 * j + 1] = q.y;
                }
#pragma unroll
                for (int kx = 0; kx < 3; ++kx) {
                    const int tap = ky * 3 + kx;
                    const ulonglong2 wr = reinterpret_cast<const ulonglong2*>(
                        &s_w[cur][(icl * 18 + tap * 2 + 0) * 64])[ct];
                    const ulonglong2 wi = reinterpret_cast<const ulonglong2*>(
                        &s_w[cur][(icl * 18 + tap * 2 + 1) * 64])[ct];
                    u64 wra[2] = { wr.x, wr.y };
                    u64 wia[2] = { wi.x, wi.y };
#pragma unroll
                    for (int jp = 0; jp < 2; ++jp) {
#pragma unroll
                        for (int k = 0; k < 4; ++k) {
                            u64 xv = vp[k + kx];
                            pRe[jp][k] = fma2(wra[jp], xv, pRe[jp][k]);
                            pIm[jp][k] = fma2(wia[jp], xv, pIm[jp][k]);
                        }
                    }
                }
            }
        }

        // ---- Kahan merge (negated-compensation; exact IEEE negation) ----
#pragma unroll
        for (int jp = 0; jp < 2; ++jp) {
#pragma unroll
            for (int k = 0; k < 4; ++k) {
                {
                    u64 y1 = add2(pRe[jp][k], ncRe[jp][k]);
                    u64 tt = add2(sRe[jp][k], y1);
                    ncRe[jp][k] = add2(add2(sRe[jp][k], NEG2(tt)), y1);
                    sRe[jp][k] = tt;
                }
                {
                    u64 y1 = add2(pIm[jp][k], ncIm[jp][k]);
                    u64 tt = add2(sIm[jp][k], y1);
                    ncIm[jp][k] = add2(add2(sIm[jp][k], NEG2(tt)), y1);
                    sIm[jp][k] = tt;
                }
            }
        }
    }

    // ---- epilogue: angle = atan2(im, re) ----
    const int y = tileY + row;
#pragma unroll
    for (int jp = 0; jp < 2; ++jp) {
#pragma unroll
        for (int lane = 0; lane < 2; ++lane) {
            const int cout = coutBase + ct * 4 + jp * 2 + lane;
            float* op = &dout[((b * COUT + cout) * HW + y) * HW + tileX + colb];
#pragma unroll
            for (int k = 0; k < 4; ++k) {
                float reLo, reHi, imLo, imHi;
                unpack2(sRe[jp][k], reLo, reHi);
                unpack2(sIm[jp][k], imLo, imHi);
                float re = lane ? reHi : reLo;
                float im = lane ? imHi : imLo;
                op[k] = atan2f(im, re);
            }
        }
    }
}

// ---------------------------------------------------------------------------
extern "C" void kernel_launch(void* const* d_in, const int* in_sizes, int n_in,
                              void* d_out, int out_size) {
    const float* x      = (const float*)d_in[0];
    const float* probe  = (const float*)d_in[1];
    const float* outang = (const float*)d_in[2];
    float* dout = (float*)d_out;

    (void)in_sizes; (void)n_in; (void)out_size;

    const int ntot = N1 + N2;
    prep_all<<<(ntot + 255) / 256, 256>>>(x, probe, outang);

    dim3 grid(4, 49, BATCH);
    ring_conv<<<grid, 256>>>(dout);
}

// round 14
// speedup vs baseline: 1.1307x; 1.0453x over previous
#include <cuda_runtime.h>
#include <math.h>
#include <stdint.h>

// Problem constants (fixed shapes from reference setup_inputs)
#define BATCH 16
#define CIN   128
#define C2    256     // 2*CIN (cos plane + sin plane)
#define COUT  256
#define HW    56
#define PIX   (HW*HW) // 3136
#define TAPS  9

typedef unsigned long long u64;

// Scratch (device globals: allocation-free per harness rules)
// Input planes stored DUPLICATED (v,v) as float2 so cp.async can copy the
// packed-FMA broadcast operand directly. 103 MB.
__device__ __align__(16) float2 g_inp2[BATCH * C2 * PIX];
// Weights, R7 layout: [(c2*9+tap)*2+ri][cout]. 4.7 MB.
__device__ __align__(16) float g_w[C2 * TAPS * 2 * COUT];

// ---- Blackwell packed f32x2 ops (two independent IEEE fp32 lanes) ----
__device__ __forceinline__ u64 fma2(u64 a, u64 b, u64 c) {
    u64 d;
    asm("fma.rn.f32x2 %0, %1, %2, %3;" : "=l"(d) : "l"(a), "l"(b), "l"(c));
    return d;
}
__device__ __forceinline__ u64 add2(u64 a, u64 b) {
    u64 d;
    asm("add.rn.f32x2 %0, %1, %2;" : "=l"(d) : "l"(a), "l"(b));
    return d;
}
#define NEG2(x) ((x) ^ 0x8000000080000000ULL)

__device__ __forceinline__ void unpack2(u64 v, float& lo, float& hi) {
    asm("mov.b64 {%0, %1}, %2;" : "=f"(lo), "=f"(hi) : "l"(v));
}

// ---- cp.async helpers ----
__device__ __forceinline__ void cp16(uint32_t saddr, const void* g) {
    asm volatile("cp.async.cg.shared.global [%0], [%1], 16;"
                 :: "r"(saddr), "l"(g));
}
// 8B copy; when szr==0 the destination is zero-filled (src not read).
__device__ __forceinline__ void cp8z(uint32_t saddr, const void* g, int szr) {
    asm volatile("cp.async.ca.shared.global [%0], [%1], 8, %2;"
                 :: "r"(saddr), "l"(g), "r"(szr));
}
#define CP_COMMIT() asm volatile("cp.async.commit_group;" ::: "memory")
#define CP_WAIT0()  asm volatile("cp.async.wait_group 0;"  ::: "memory")

// ---------------------------------------------------------------------------
// Merged prep kernel (2 launches total).
//  i < N1: input planes  cos(x)->[0,128), sin(x)->[128,256), duplicated (v,v)
//  else  : trig weight products (R7 layout)
// probe/out layout: (1, Cin, Cout, 1, 1, 3, 3) -> flat ((cin*COUT+cout)*9+tap)
// ---------------------------------------------------------------------------
#define N1 (BATCH * CIN * PIX)
#define N2 (CIN * COUT * TAPS)

__global__ void prep_all(const float* __restrict__ x,
                         const float* __restrict__ probe,
                         const float* __restrict__ outang) {
    int i = blockIdx.x * blockDim.x + threadIdx.x;
    if (i < N1) {
        float v = x[i];
        int b   = i / (CIN * PIX);
        int rem = i % (CIN * PIX);
        int c   = rem / PIX;
        int p   = rem % PIX;
        float s, cs;
        sincosf(v, &s, &cs);
        g_inp2[(b * C2 + c) * PIX + p]        = make_float2(cs, cs);
        g_inp2[(b * C2 + c + CIN) * PIX + p]  = make_float2(s, s);
    } else {
        int j = i - N1;
        if (j >= N2) return;
        int cin  = j / (COUT * TAPS);
        int rem  = j % (COUT * TAPS);
        int cout = rem / TAPS;
        int tap  = rem % TAPS;
        float p = probe[j];
        float o = outang[j];
        float sp, cp, so, co;
        sincosf(p, &sp, &cp);
        sincosf(o, &so, &co);
        g_w[(( cin        * TAPS + tap) * 2 + 0) * COUT + cout] = cp * co;
        g_w[(( cin        * TAPS + tap) * 2 + 1) * COUT + cout] = cp * so;
        g_w[(((cin + CIN) * TAPS + tap) * 2 + 0) * COUT + cout] = sp * co;
        g_w[(((cin + CIN) * TAPS + tap) * 2 + 1) * COUT + cout] = sp * so;
    }
}

// ---------------------------------------------------------------------------
// Main conv kernel: R7 compute (bit-identical), cp.async double-buffered
// smem pipeline, now capped at 128 regs for 2 blocks/SM (4 warps/SMSP):
// __launch_bounds__(256, 2) + per-chunk recomputed copy descriptors
// (no persistent index/offset registers).
//
// Grid: (4 cout-quarters of 64, 49 spatial tiles of 8x8, 16 batch).
// Block: 256 threads = 16 cout-lanes x 16 pixel-lanes (R7 mapping).
// ---------------------------------------------------------------------------
#define CHUNK 4
#define W_FLOATS (CHUNK * TAPS * 2 * 64)    // 4608 floats (64-cout slice)
#define W_VEC4   (W_FLOATS / 4)             // 1152 float4
#define IN_PTS   (CHUNK * 10 * 10)          // 400 halo points (float2 (v,v))
#define NCHUNK   (C2 / CHUNK)               // 64

__global__ __launch_bounds__(256, 2)
void ring_conv(float* __restrict__ dout) {
    __shared__ __align__(16) float  s_w[2][W_FLOATS];
    __shared__ __align__(16) float2 s_in[2][IN_PTS];

    const int tid  = threadIdx.x;
    const int ct   = tid & 15;          // cout lane (4 couts each)
    const int pl   = tid >> 4;          // pixel lane 0..15
    const int row  = pl >> 1;           // 0..7
    const int colb = (pl & 1) * 4;      // 0 or 4

    const int coutBase = blockIdx.x * 64;
    const int t     = blockIdx.y;
    const int tileY = (t / 7) * 8;
    const int tileX = (t % 7) * 8;
    const int b     = blockIdx.z;

    uint32_t s_in_base = (uint32_t)__cvta_generic_to_shared(&s_in[0][0]);
    uint32_t s_w_base  = (uint32_t)__cvta_generic_to_shared(&s_w[0][0]);
    const uint32_t IN_BUF_B = IN_PTS * 8;        // bytes per input buffer
    const uint32_t W_BUF_B  = W_FLOATS * 4;      // bytes per weight buffer

    // Issue all cp.async copies for one chunk into buffer `buf`.
    // Descriptors recomputed per call (saves ~10 persistent regs; ~6 IMADs).
    auto issue_chunk = [&](int chunk, int buf) {
        const int ic0 = chunk * CHUNK;
        // inputs (8B, zero-filled when OOB)
#pragma unroll
        for (int it = 0; it < 2; ++it) {
            int i = tid + it * 256;
            if (i < IN_PTS) {
                int icl = i / 100;
                int p   = i % 100;
                int gy  = tileY + p / 10 - 1;
                int gx  = tileX + p % 10 - 1;
                bool ok = (unsigned)gy < (unsigned)HW && (unsigned)gx < (unsigned)HW;
                const float2* g = &g_inp2[(long)(b * C2 + ic0 + icl) * PIX
                                          + (ok ? gy * HW + gx : 0)];
                cp8z(s_in_base + buf * IN_BUF_B + i * 8, g, ok ? 8 : 0);
            }
        }
        // weights (16B)
#pragma unroll
        for (int it = 0; it < 5; ++it) {
            int i = tid + it * 256;          // float4 index
            if (i < W_VEC4) {
                int f   = i * 4;
                int icl = f / (TAPS * 2 * 64);
                int r   = (f % (TAPS * 2 * 64)) / 64;   // tap*2 + ri
                int col = f & 63;
                cp16(s_w_base + buf * W_BUF_B + i * 16,
                     &g_w[((ic0 + icl) * 18 + r) * COUT + coutBase + col]);
            }
        }
        CP_COMMIT();
    };

    // Prologue: start chunk 0 into buffer 0.
    issue_chunk(0, 0);

    // s = main sum, nc = NEGATED Kahan compensation
    u64 sRe[2][4], sIm[2][4];
    u64 ncRe[2][4], ncIm[2][4];
#pragma unroll
    for (int jp = 0; jp < 2; ++jp)
#pragma unroll
        for (int k = 0; k < 4; ++k) {
            sRe[jp][k] = 0ull; sIm[jp][k] = 0ull;
            ncRe[jp][k] = 0ull; ncIm[jp][k] = 0ull;
        }

    for (int chunk = 0; chunk < NCHUNK; ++chunk) {
        const int cur = chunk & 1;

        CP_WAIT0();        // this chunk's copies (only group in flight) done
        __syncthreads();   // visibility + everyone done reading other buffer

        if (chunk + 1 < NCHUNK)
            issue_chunk(chunk + 1, cur ^ 1);   // flies during compute below

        // ---- compute chunk partial (packed FMA, bit-identical to R7) ----
        u64 pRe[2][4], pIm[2][4];
#pragma unroll
        for (int jp = 0; jp < 2; ++jp)
#pragma unroll
            for (int k = 0; k < 4; ++k) { pRe[jp][k] = 0ull; pIm[jp][k] = 0ull; }

#pragma unroll
        for (int icl = 0; icl < CHUNK; ++icl) {
            const float2* in_base = &s_in[cur][icl * 100];
#pragma unroll
            for (int ky = 0; ky < 3; ++ky) {
                u64 vp[6];
                const ulonglong2* rp = reinterpret_cast<const ulonglong2*>(
                    &in_base[(row + ky) * 10 + colb]);
#pragma unroll
                for (int j = 0; j < 3; ++j) {
                    ulonglong2 q = rp[j];
                    vp[2 * j]     = q.x;
                    vp[2 * j + 1] = q.y;
                }
#pragma unroll
                for (int kx = 0; kx < 3; ++kx) {
                    const int tap = ky * 3 + kx;
                    const ulonglong2 wr = reinterpret_cast<const ulonglong2*>(
                        &s_w[cur][(icl * 18 + tap * 2 + 0) * 64])[ct];
                    const ulonglong2 wi = reinterpret_cast<const ulonglong2*>(
                        &s_w[cur][(icl * 18 + tap * 2 + 1) * 64])[ct];
                    u64 wra[2] = { wr.x, wr.y };
                    u64 wia[2] = { wi.x, wi.y };
#pragma unroll
                    for (int jp = 0; jp < 2; ++jp) {
#pragma unroll
                        for (int k = 0; k < 4; ++k) {
                            u64 xv = vp[k + kx];
                            pRe[jp][k] = fma2(wra[jp], xv, pRe[jp][k]);
                            pIm[jp][k] = fma2(wia[jp], xv, pIm[jp][k]);
                        }
                    }
                }
            }
        }

        // ---- Kahan merge (negated-compensation; exact IEEE negation) ----
#pragma unroll
        for (int jp = 0; jp < 2; ++jp) {
#pragma unroll
            for (int k = 0; k < 4; ++k) {
                {
                    u64 y1 = add2(pRe[jp][k], ncRe[jp][k]);
                    u64 tt = add2(sRe[jp][k], y1);
                    ncRe[jp][k] = add2(add2(sRe[jp][k], NEG2(tt)), y1);
                    sRe[jp][k] = tt;
                }
                {
                    u64 y1 = add2(pIm[jp][k], ncIm[jp][k]);
                    u64 tt = add2(sIm[jp][k], y1);
                    ncIm[jp][k] = add2(add2(sIm[jp][k], NEG2(tt)), y1);
                    sIm[jp][k] = tt;
                }
            }
        }
    }

    // ---- epilogue: angle = atan2(im, re) ----
    const int y = tileY + row;
#pragma unroll
    for (int jp = 0; jp < 2; ++jp) {
#pragma unroll
        for (int lane = 0; lane < 2; ++lane) {
            const int cout = coutBase + ct * 4 + jp * 2 + lane;
            float* op = &dout[((b * COUT + cout) * HW + y) * HW + tileX + colb];
#pragma unroll
            for (int k = 0; k < 4; ++k) {
                float reLo, reHi, imLo, imHi;
                unpack2(sRe[jp][k], reLo, reHi);
                unpack2(sIm[jp][k], imLo, imHi);
                float re = lane ? reHi : reLo;
                float im = lane ? imHi : imLo;
                op[k] = atan2f(im, re);
            }
        }
    }
}

// ---------------------------------------------------------------------------
extern "C" void kernel_launch(void* const* d_in, const int* in_sizes, int n_in,
                              void* d_out, int out_size) {
    const float* x      = (const float*)d_in[0];
    const float* probe  = (const float*)d_in[1];
    const float* outang = (const float*)d_in[2];
    float* dout = (float*)d_out;

    (void)in_sizes; (void)n_in; (void)out_size;

    const int ntot = N1 + N2;
    prep_all<<<(ntot + 255) / 256, 256>>>(x, probe, outang);

    dim3 grid(4, 49, BATCH);
    ring_conv<<<grid, 256>>>(dout);
}